// round 14
// baseline (speedup 1.0000x reference)
#include <cuda_runtime.h>
#include <cuda_fp16.h>
#include <cstdint>

#define N_NODES   20000
#define M_PAD     20096      // 314 * 64
#define IN_DIM    256
#define OUT_DIM   256
#define FOLD_DIM  128        // 32 q-groups * 4 bases
#define K_DIM     1024       // 8 relations * 128

// Scratch (static device globals — no allocation allowed)
__device__ __half g_hf[N_NODES * FOLD_DIM];        // folded h  [N, 128] fp16
__device__ __half g_U [(size_t)M_PAD * K_DIM];     // aggregated [M_PAD, 1024] fp16
__device__ __half g_Bt[(size_t)OUT_DIM * K_DIM];   // basis^T, K-major, fp16

// ---------------------------------------------------------------------------
// Kernel 1: fold h with w_comp.  hf[n, q*4+b] = sum_p h[n, q*8+p] * w_comp[p,b]
// ---------------------------------------------------------------------------
__global__ void fold_kernel(const float* __restrict__ h,
                            const float* __restrict__ w_comp, int N) {
    __shared__ float wc[32];
    if (threadIdx.x < 32) wc[threadIdx.x] = w_comp[threadIdx.x];
    __syncthreads();

    int idx = blockIdx.x * blockDim.x + threadIdx.x;
    if (idx >= N * 32) return;
    int n = idx >> 5;
    int q = idx & 31;

    const float4* hp = reinterpret_cast<const float4*>(h + (size_t)n * IN_DIM + q * 8);
    float4 h0 = hp[0];
    float4 h1 = hp[1];
    float hv[8] = {h0.x, h0.y, h0.z, h0.w, h1.x, h1.y, h1.z, h1.w};

    float o[4];
    #pragma unroll
    for (int b = 0; b < 4; b++) {
        float s = 0.f;
        #pragma unroll
        for (int p = 0; p < 8; p++) s += hv[p] * wc[p * 4 + b];
        o[b] = s;
    }
    __half2 p0 = __floats2half2_rn(o[0], o[1]);
    __half2 p1 = __floats2half2_rn(o[2], o[3]);
    __half2* d = reinterpret_cast<__half2*>(g_hf + (size_t)n * FOLD_DIM + q * 4);
    d[0] = p0;
    d[1] = p1;
}

// ---------------------------------------------------------------------------
// Kernel 2: transpose basis [1024,256] -> g_Bt [256,1024] (K-major) as fp16.
// ---------------------------------------------------------------------------
__global__ void transpose_kernel(const float* __restrict__ basis) {
    __shared__ float t[32][33];
    int bx = blockIdx.x;
    int by = blockIdx.y;
    int x = threadIdx.x;
    int y = threadIdx.y;
    #pragma unroll
    for (int i = 0; i < 4; i++)
        t[y + i * 8][x] = basis[(size_t)(bx * 32 + y + i * 8) * OUT_DIM + by * 32 + x];
    __syncthreads();
    #pragma unroll
    for (int i = 0; i < 4; i++)
        g_Bt[(size_t)(by * 32 + y + i * 8) * K_DIM + bx * 32 + x] =
            __float2half_rn(t[x][y + i * 8]);
}

// ---------------------------------------------------------------------------
// Kernel 3: edge scatter, fp16. 8 lanes per edge, TWO red.add.noftz.v4.f16x2
// per thread (2x MLP vs one), 4 edges per warp.
// ---------------------------------------------------------------------------
__global__ void scatter_kernel(const int* __restrict__ src,
                               const int* __restrict__ dst,
                               const int* __restrict__ etype, int E) {
    int warp = (blockIdx.x * blockDim.x + threadIdx.x) >> 5;
    int lane = threadIdx.x & 31;
    int e = warp * 4 + (lane >> 3);      // 4 edges per warp
    int l = lane & 7;                    // 8 lanes cover 128 halves (16 each)
    if (e >= E) return;

    int s = __ldg(src + e);
    int d = __ldg(dst + e);
    int r = __ldg(etype + e);

    const uint4* vp = reinterpret_cast<const uint4*>(g_hf + (size_t)s * FOLD_DIM + l * 16);
    uint4 v0 = vp[0];
    uint4 v1 = vp[1];
    __half* up = g_U + (size_t)d * K_DIM + r * FOLD_DIM + l * 16;
    asm volatile("red.global.add.noftz.v4.f16x2 [%0], {%1, %2, %3, %4};"
                 :: "l"(up), "r"(v0.x), "r"(v0.y), "r"(v0.z), "r"(v0.w)
                 : "memory");
    asm volatile("red.global.add.noftz.v4.f16x2 [%0], {%1, %2, %3, %4};"
                 :: "l"(up + 8), "r"(v1.x), "r"(v1.y), "r"(v1.z), "r"(v1.w)
                 : "memory");
}

// ---------------------------------------------------------------------------
// Kernel 4: fp16 tensor-core GEMM + bias + relu.
// out[M,256] = relu(U[M,1024] @ Bt^T + bias)
// CTA 64x64, 128 threads, 2x2 warp grid (warp tile 32x32), 6 CTAs/SM.
// BK=64, 2-stage cp.async, SW128 smem, fully precomputed/literal addressing.
// ---------------------------------------------------------------------------
#define GBM 64
#define GBN 64
#define GBK 64
#define STAGE_BYTES (GBM * 128)                       // 8192 B per operand-stage
#define GEMM_SMEM_BYTES (2 * 2 * STAGE_BYTES)         // 32768 B

#define SWZ(o) ((o) ^ (((o) >> 3) & 0x70))

__device__ __forceinline__ uint32_t smem_u32(const void* p) {
    return (uint32_t)__cvta_generic_to_shared(p);
}

__global__ __launch_bounds__(128, 6)
void gemm_tc_kernel(const __half* __restrict__ Bt,
                    const float* __restrict__ bias,
                    float* __restrict__ out, int M) {
    extern __shared__ char smem[];
    char* As = smem;                        // stages at +0, +8192
    char* Bs = smem + 2 * STAGE_BYTES;      // stages at +0, +8192

    int tid  = threadIdx.x;
    int lane = tid & 31;
    int warp = tid >> 5;
    int wm = warp & 1;                      // rows wm*32
    int wn = warp >> 1;                     // cols wn*32
    int bm = blockIdx.y * GBM;
    int bn = blockIdx.x * GBN;

    float acc[2][4][4];                     // [mf][nf][4]
    #pragma unroll
    for (int mf = 0; mf < 2; mf++)
        #pragma unroll
        for (int nf = 0; nf < 4; nf++)
            #pragma unroll
            for (int i = 0; i < 4; i++) acc[mf][nf][i] = 0.f;

    // ---- staging bases (all further offsets are compile-time literals) ----
    int r0  = tid >> 3;                    // 0..15; covers rows r0 + 16i
    int seg = tid & 7;
    uint32_t c_st = (uint32_t)(r0 & 7) << 4;   // swizzle const: invariant in i
    uint32_t daA = smem_u32(As) + r0 * 128 + ((uint32_t)(seg * 16) ^ c_st);
    uint32_t daB = smem_u32(Bs) + r0 * 128 + ((uint32_t)(seg * 16) ^ c_st);
    const __half* gA = g_U + (size_t)(bm + r0) * K_DIM + seg * 8;
    const __half* gB = Bt + (size_t)(bn + r0) * K_DIM + seg * 8;

    #define ISSUE_STAGE(STGOFF, KOFF)                                           \
        do {                                                                    \
            _Pragma("unroll")                                                   \
            for (int i = 0; i < 4; i++) {                                       \
                asm volatile("cp.async.cg.shared.global [%0], [%1], 16;"        \
                             :: "r"(daA + (STGOFF) + i * 2048),                 \
                                "l"(gA + (KOFF) + i * 16 * K_DIM) : "memory");  \
                asm volatile("cp.async.cg.shared.global [%0], [%1], 16;"        \
                             :: "r"(daB + (STGOFF) + i * 2048),                 \
                                "l"(gB + (KOFF) + i * 16 * K_DIM) : "memory");  \
            }                                                                   \
            asm volatile("cp.async.commit_group;" ::: "memory");                \
        } while (0)

    // ---- fragment LDSM addresses, stage 0 (loop-invariant) ----
    int frow = lane & 15;
    int fkb  = (lane >> 4) * 16;
    uint32_t aaddr[2][4], baddr[2][4];
    {
        uint32_t abase = smem_u32(As);
        uint32_t bbase = smem_u32(Bs);
        #pragma unroll
        for (int mf = 0; mf < 2; mf++) {
            int row = wm * 32 + mf * 16 + frow;
            uint32_t c = (uint32_t)(row & 7) << 4;
            #pragma unroll
            for (int ks = 0; ks < 4; ks++)
                aaddr[mf][ks] = abase + row * 128 + ((uint32_t)(ks * 32 + fkb) ^ c);
        }
        #pragma unroll
        for (int p = 0; p < 2; p++) {
            int row = wn * 32 + p * 16 + frow;
            uint32_t c = (uint32_t)(row & 7) << 4;
            #pragma unroll
            for (int ks = 0; ks < 4; ks++)
                baddr[p][ks] = bbase + row * 128 + ((uint32_t)(ks * 32 + fkb) ^ c);
        }
    }

    #define COMPUTE(COFF)                                                           \
        do {                                                                        \
            _Pragma("unroll")                                                       \
            for (int ks = 0; ks < 4; ks++) {                                        \
                uint32_t afr[2][4];                                                 \
                _Pragma("unroll")                                                   \
                for (int mf = 0; mf < 2; mf++)                                      \
                    asm volatile(                                                   \
                        "ldmatrix.sync.aligned.m8n8.x4.shared.b16 {%0,%1,%2,%3}, [%4];" \
                        : "=r"(afr[mf][0]), "=r"(afr[mf][1]),                       \
                          "=r"(afr[mf][2]), "=r"(afr[mf][3])                        \
                        : "r"(aaddr[mf][ks] + (COFF)));                             \
                uint32_t bfr[4][2];                                                 \
                _Pragma("unroll")                                                   \
                for (int p = 0; p < 2; p++) {                                       \
                    uint32_t r0_, r1_, r2_, r3_;                                    \
                    asm volatile(                                                   \
                        "ldmatrix.sync.aligned.m8n8.x4.shared.b16 {%0,%1,%2,%3}, [%4];" \
                        : "=r"(r0_), "=r"(r1_), "=r"(r2_), "=r"(r3_)                \
                        : "r"(baddr[p][ks] + (COFF)));                              \
                    bfr[2 * p][0] = r0_; bfr[2 * p + 1][0] = r1_;                   \
                    bfr[2 * p][1] = r2_; bfr[2 * p + 1][1] = r3_;                   \
                }                                                                   \
                _Pragma("unroll")                                                   \
                for (int mf = 0; mf < 2; mf++)                                      \
                    _Pragma("unroll")                                               \
                    for (int nf = 0; nf < 4; nf++)                                  \
                        asm volatile(                                               \
                            "mma.sync.aligned.m16n8k16.row.col.f32.f16.f16.f32 "    \
                            "{%0,%1,%2,%3}, {%4,%5,%6,%7}, {%8,%9}, {%0,%1,%2,%3};" \
                            : "+f"(acc[mf][nf][0]), "+f"(acc[mf][nf][1]),           \
                              "+f"(acc[mf][nf][2]), "+f"(acc[mf][nf][3])            \
                            : "r"(afr[mf][0]), "r"(afr[mf][1]),                     \
                              "r"(afr[mf][2]), "r"(afr[mf][3]),                     \
                              "r"(bfr[nf][0]), "r"(bfr[nf][1]));                    \
            }                                                                       \
        } while (0)

    // prologue: stage 0 <- k=0
    ISSUE_STAGE(0, 0);

    // unroll-by-2: 16 k-chunks as 8 outer iterations with explicit stage parity
    for (int it2 = 0; it2 < 8; ++it2) {
        asm volatile("cp.async.wait_group 0;" ::: "memory");
        __syncthreads();
        ISSUE_STAGE(STAGE_BYTES, 64);
        COMPUTE(0);

        asm volatile("cp.async.wait_group 0;" ::: "memory");
        __syncthreads();
        if (it2 < 7) ISSUE_STAGE(0, 128);
        COMPUTE(STAGE_BYTES);

        gA += 128;
        gB += 128;
    }

    // epilogue: + bias, relu
    #pragma unroll
    for (int mf = 0; mf < 2; mf++) {
        int row0 = bm + wm * 32 + mf * 16 + (lane >> 2);
        #pragma unroll
        for (int nf = 0; nf < 4; nf++) {
            int col = bn + wn * 32 + nf * 8 + (lane & 3) * 2;
            float b0 = __ldg(bias + col);
            float b1 = __ldg(bias + col + 1);
            if (row0 < M) {
                float2 o;
                o.x = fmaxf(acc[mf][nf][0] + b0, 0.f);
                o.y = fmaxf(acc[mf][nf][1] + b1, 0.f);
                *reinterpret_cast<float2*>(out + (size_t)row0 * OUT_DIM + col) = o;
            }
            if (row0 + 8 < M) {
                float2 o;
                o.x = fmaxf(acc[mf][nf][2] + b0, 0.f);
                o.y = fmaxf(acc[mf][nf][3] + b1, 0.f);
                *reinterpret_cast<float2*>(out + (size_t)(row0 + 8) * OUT_DIM + col) = o;
            }
        }
    }
}

// ---------------------------------------------------------------------------
extern "C" void kernel_launch(void* const* d_in, const int* in_sizes, int n_in,
                              void* d_out, int out_size) {
    const float* h      = (const float*)d_in[0];
    const float* basis  = (const float*)d_in[1];
    const float* w_comp = (const float*)d_in[2];
    const float* bias   = (const float*)d_in[3];
    const int*   src    = (const int*)d_in[4];
    const int*   dst    = (const int*)d_in[5];
    const int*   etype  = (const int*)d_in[6];
    float* out = (float*)d_out;

    int N = in_sizes[0] / IN_DIM;   // 20000
    int E = in_sizes[4];            // 320000

    static cudaStream_t s1 = nullptr, s2 = nullptr;
    static cudaEvent_t e0 = nullptr, e1 = nullptr, e2 = nullptr;
    static bool init_done = false;
    if (!init_done) {
        cudaFuncSetAttribute(gemm_tc_kernel,
                             cudaFuncAttributeMaxDynamicSharedMemorySize,
                             GEMM_SMEM_BYTES);
        cudaStreamCreateWithFlags(&s1, cudaStreamNonBlocking);
        cudaStreamCreateWithFlags(&s2, cudaStreamNonBlocking);
        cudaEventCreateWithFlags(&e0, cudaEventDisableTiming);
        cudaEventCreateWithFlags(&e1, cudaEventDisableTiming);
        cudaEventCreateWithFlags(&e2, cudaEventDisableTiming);
        init_done = true;
    }

    void* uptr = nullptr;
    cudaGetSymbolAddress(&uptr, g_U);
    __half* btp = nullptr;
    cudaGetSymbolAddress((void**)&btp, g_Bt);

    // fork: memset U on s1; transpose on s2 (joined only before GEMM)
    cudaEventRecord(e0, 0);
    cudaStreamWaitEvent(s1, e0, 0);
    cudaStreamWaitEvent(s2, e0, 0);

    cudaMemsetAsync(uptr, 0, (size_t)M_PAD * K_DIM * sizeof(__half), s1);  // #1
    cudaEventRecord(e1, s1);

    fold_kernel<<<(N * 32 + 255) / 256, 256>>>(h, w_comp, N);              // #2

    transpose_kernel<<<dim3(32, 8), dim3(32, 8), 0, s2>>>(basis);          // #3
    cudaEventRecord(e2, s2);

    cudaStreamWaitEvent(0, e1, 0);   // scatter needs zeroed U (+ fold on main)

    scatter_kernel<<<(E + 7) / 8, 256>>>(src, dst, etype, E);              // #4

    cudaStreamWaitEvent(0, e2, 0);   // GEMM needs Bt

    dim3 grid(OUT_DIM / GBN, M_PAD / GBM);   // (4, 314)
    gemm_tc_kernel<<<grid, 128, GEMM_SMEM_BYTES>>>(btp, bias, out, N);     // #5 (ncu)
}

// round 15
// speedup vs baseline: 1.2685x; 1.2685x over previous
#include <cuda_runtime.h>
#include <cuda_fp16.h>
#include <cstdint>

#define N_NODES   20000
#define M_PAD     20096      // 314 * 64
#define IN_DIM    256
#define OUT_DIM   256
#define FOLD_DIM  128        // 32 q-groups * 4 bases
#define K_DIM     1024       // 8 relations * 128

// Scratch (static device globals — no allocation allowed)
__device__ __half g_hf[N_NODES * FOLD_DIM];        // folded h  [N, 128] fp16
__device__ __half g_U [(size_t)M_PAD * K_DIM];     // aggregated [M_PAD, 1024] fp16
__device__ __half g_Bt[(size_t)OUT_DIM * K_DIM];   // basis^T, K-major, fp16

// ---------------------------------------------------------------------------
// Kernel 1: fold h with w_comp.  hf[n, q*4+b] = sum_p h[n, q*8+p] * w_comp[p,b]
// Each thread handles TWO q-groups (4 independent float4 loads -> MLP 4).
// ---------------------------------------------------------------------------
__global__ void fold_kernel(const float* __restrict__ h,
                            const float* __restrict__ w_comp, int N) {
    __shared__ float wc[32];
    if (threadIdx.x < 32) wc[threadIdx.x] = w_comp[threadIdx.x];
    __syncthreads();

    int idx = blockIdx.x * blockDim.x + threadIdx.x;   // over N*16 (n, q-pair)
    if (idx >= N * 16) return;
    int n  = idx >> 4;
    int q2 = idx & 15;                                 // q = 2*q2, 2*q2+1

    const float4* hp = reinterpret_cast<const float4*>(
        h + (size_t)n * IN_DIM + q2 * 16);
    float4 hv4[4];
    hv4[0] = hp[0]; hv4[1] = hp[1]; hv4[2] = hp[2]; hv4[3] = hp[3];
    const float* hv = reinterpret_cast<const float*>(hv4);   // 16 floats

    __half2 o[4];
    #pragma unroll
    for (int g = 0; g < 2; g++) {            // the two q-groups
        float r[4];
        #pragma unroll
        for (int b = 0; b < 4; b++) {
            float s = 0.f;
            #pragma unroll
            for (int p = 0; p < 8; p++) s += hv[g * 8 + p] * wc[p * 4 + b];
            r[b] = s;
        }
        o[g * 2 + 0] = __floats2half2_rn(r[0], r[1]);
        o[g * 2 + 1] = __floats2half2_rn(r[2], r[3]);
    }
    *reinterpret_cast<uint4*>(g_hf + (size_t)n * FOLD_DIM + q2 * 8) =
        *reinterpret_cast<const uint4*>(o);
}

// ---------------------------------------------------------------------------
// Kernel 2: transpose basis [1024,256] -> g_Bt [256,1024] (K-major) as fp16.
// ---------------------------------------------------------------------------
__global__ void transpose_kernel(const float* __restrict__ basis) {
    __shared__ float t[32][33];
    int bx = blockIdx.x;
    int by = blockIdx.y;
    int x = threadIdx.x;
    int y = threadIdx.y;
    #pragma unroll
    for (int i = 0; i < 4; i++)
        t[y + i * 8][x] = basis[(size_t)(bx * 32 + y + i * 8) * OUT_DIM + by * 32 + x];
    __syncthreads();
    #pragma unroll
    for (int i = 0; i < 4; i++)
        g_Bt[(size_t)(by * 32 + y + i * 8) * K_DIM + bx * 32 + x] =
            __float2half_rn(t[x][y + i * 8]);
}

// ---------------------------------------------------------------------------
// Kernel 3: edge scatter, fp16 (R13-proven shape).
// 16 lanes per edge, contiguous uint4 gather + one red.add.noftz.v4.f16x2.
// ---------------------------------------------------------------------------
__global__ void scatter_kernel(const int* __restrict__ src,
                               const int* __restrict__ dst,
                               const int* __restrict__ etype, int E) {
    int warp = (blockIdx.x * blockDim.x + threadIdx.x) >> 5;
    int lane = threadIdx.x & 31;
    int e = warp * 2 + (lane >> 4);
    int l = lane & 15;
    if (e >= E) return;

    int s = __ldg(src + e);
    int d = __ldg(dst + e);
    int r = __ldg(etype + e);

    uint4 v = *reinterpret_cast<const uint4*>(g_hf + (size_t)s * FOLD_DIM + l * 8);
    __half* up = g_U + (size_t)d * K_DIM + r * FOLD_DIM + l * 8;
    asm volatile("red.global.add.noftz.v4.f16x2 [%0], {%1, %2, %3, %4};"
                 :: "l"(up), "r"(v.x), "r"(v.y), "r"(v.z), "r"(v.w)
                 : "memory");
}

// ---------------------------------------------------------------------------
// Kernel 4: fp16 tensor-core GEMM + bias + relu.
// out[M,256] = relu(U[M,1024] @ Bt^T + bias)
// CTA 64x64, 128 threads, 2x2 warp grid (warp tile 32x32), 6 CTAs/SM.
// BK=64, 2-stage cp.async, SW128 smem, fully precomputed/literal addressing.
// ---------------------------------------------------------------------------
#define GBM 64
#define GBN 64
#define GBK 64
#define STAGE_BYTES (GBM * 128)                       // 8192 B per operand-stage
#define GEMM_SMEM_BYTES (2 * 2 * STAGE_BYTES)         // 32768 B

#define SWZ(o) ((o) ^ (((o) >> 3) & 0x70))

__device__ __forceinline__ uint32_t smem_u32(const void* p) {
    return (uint32_t)__cvta_generic_to_shared(p);
}

__global__ __launch_bounds__(128, 6)
void gemm_tc_kernel(const __half* __restrict__ Bt,
                    const float* __restrict__ bias,
                    float* __restrict__ out, int M) {
    extern __shared__ char smem[];
    char* As = smem;                        // stages at +0, +8192
    char* Bs = smem + 2 * STAGE_BYTES;      // stages at +0, +8192

    int tid  = threadIdx.x;
    int lane = tid & 31;
    int warp = tid >> 5;
    int wm = warp & 1;                      // rows wm*32
    int wn = warp >> 1;                     // cols wn*32
    int bm = blockIdx.y * GBM;
    int bn = blockIdx.x * GBN;

    float acc[2][4][4];                     // [mf][nf][4]
    #pragma unroll
    for (int mf = 0; mf < 2; mf++)
        #pragma unroll
        for (int nf = 0; nf < 4; nf++)
            #pragma unroll
            for (int i = 0; i < 4; i++) acc[mf][nf][i] = 0.f;

    // ---- staging bases (all further offsets are compile-time literals) ----
    int r0  = tid >> 3;                    // 0..15; covers rows r0 + 16i
    int seg = tid & 7;
    uint32_t c_st = (uint32_t)(r0 & 7) << 4;   // swizzle const: invariant in i
    uint32_t daA = smem_u32(As) + r0 * 128 + ((uint32_t)(seg * 16) ^ c_st);
    uint32_t daB = smem_u32(Bs) + r0 * 128 + ((uint32_t)(seg * 16) ^ c_st);
    const __half* gA = g_U + (size_t)(bm + r0) * K_DIM + seg * 8;
    const __half* gB = Bt + (size_t)(bn + r0) * K_DIM + seg * 8;

    #define ISSUE_STAGE(STGOFF, KOFF)                                           \
        do {                                                                    \
            _Pragma("unroll")                                                   \
            for (int i = 0; i < 4; i++) {                                       \
                asm volatile("cp.async.cg.shared.global [%0], [%1], 16;"        \
                             :: "r"(daA + (STGOFF) + i * 2048),                 \
                                "l"(gA + (KOFF) + i * 16 * K_DIM) : "memory");  \
                asm volatile("cp.async.cg.shared.global [%0], [%1], 16;"        \
                             :: "r"(daB + (STGOFF) + i * 2048),                 \
                                "l"(gB + (KOFF) + i * 16 * K_DIM) : "memory");  \
            }                                                                   \
            asm volatile("cp.async.commit_group;" ::: "memory");                \
        } while (0)

    // ---- fragment LDSM addresses, stage 0 (loop-invariant) ----
    int frow = lane & 15;
    int fkb  = (lane >> 4) * 16;
    uint32_t aaddr[2][4], baddr[2][4];
    {
        uint32_t abase = smem_u32(As);
        uint32_t bbase = smem_u32(Bs);
        #pragma unroll
        for (int mf = 0; mf < 2; mf++) {
            int row = wm * 32 + mf * 16 + frow;
            uint32_t c = (uint32_t)(row & 7) << 4;
            #pragma unroll
            for (int ks = 0; ks < 4; ks++)
                aaddr[mf][ks] = abase + row * 128 + ((uint32_t)(ks * 32 + fkb) ^ c);
        }
        #pragma unroll
        for (int p = 0; p < 2; p++) {
            int row = wn * 32 + p * 16 + frow;
            uint32_t c = (uint32_t)(row & 7) << 4;
            #pragma unroll
            for (int ks = 0; ks < 4; ks++)
                baddr[p][ks] = bbase + row * 128 + ((uint32_t)(ks * 32 + fkb) ^ c);
        }
    }

    #define COMPUTE(COFF)                                                           \
        do {                                                                        \
            _Pragma("unroll")                                                       \
            for (int ks = 0; ks < 4; ks++) {                                        \
                uint32_t afr[2][4];                                                 \
                _Pragma("unroll")                                                   \
                for (int mf = 0; mf < 2; mf++)                                      \
                    asm volatile(                                                   \
                        "ldmatrix.sync.aligned.m8n8.x4.shared.b16 {%0,%1,%2,%3}, [%4];" \
                        : "=r"(afr[mf][0]), "=r"(afr[mf][1]),                       \
                          "=r"(afr[mf][2]), "=r"(afr[mf][3])                        \
                        : "r"(aaddr[mf][ks] + (COFF)));                             \
                uint32_t bfr[4][2];                                                 \
                _Pragma("unroll")                                                   \
                for (int p = 0; p < 2; p++) {                                       \
                    uint32_t r0_, r1_, r2_, r3_;                                    \
                    asm volatile(                                                   \
                        "ldmatrix.sync.aligned.m8n8.x4.shared.b16 {%0,%1,%2,%3}, [%4];" \
                        : "=r"(r0_), "=r"(r1_), "=r"(r2_), "=r"(r3_)                \
                        : "r"(baddr[p][ks] + (COFF)));                              \
                    bfr[2 * p][0] = r0_; bfr[2 * p + 1][0] = r1_;                   \
                    bfr[2 * p][1] = r2_; bfr[2 * p + 1][1] = r3_;                   \
                }                                                                   \
                _Pragma("unroll")                                                   \
                for (int mf = 0; mf < 2; mf++)                                      \
                    _Pragma("unroll")                                               \
                    for (int nf = 0; nf < 4; nf++)                                  \
                        asm volatile(                                               \
                            "mma.sync.aligned.m16n8k16.row.col.f32.f16.f16.f32 "    \
                            "{%0,%1,%2,%3}, {%4,%5,%6,%7}, {%8,%9}, {%0,%1,%2,%3};" \
                            : "+f"(acc[mf][nf][0]), "+f"(acc[mf][nf][1]),           \
                              "+f"(acc[mf][nf][2]), "+f"(acc[mf][nf][3])            \
                            : "r"(afr[mf][0]), "r"(afr[mf][1]),                     \
                              "r"(afr[mf][2]), "r"(afr[mf][3]),                     \
                              "r"(bfr[nf][0]), "r"(bfr[nf][1]));                    \
            }                                                                       \
        } while (0)

    // prologue: stage 0 <- k=0
    ISSUE_STAGE(0, 0);

    // unroll-by-2: 16 k-chunks as 8 outer iterations with explicit stage parity
    for (int it2 = 0; it2 < 8; ++it2) {
        asm volatile("cp.async.wait_group 0;" ::: "memory");
        __syncthreads();
        ISSUE_STAGE(STAGE_BYTES, 64);
        COMPUTE(0);

        asm volatile("cp.async.wait_group 0;" ::: "memory");
        __syncthreads();
        if (it2 < 7) ISSUE_STAGE(0, 128);
        COMPUTE(STAGE_BYTES);

        gA += 128;
        gB += 128;
    }

    // epilogue: + bias, relu
    #pragma unroll
    for (int mf = 0; mf < 2; mf++) {
        int row0 = bm + wm * 32 + mf * 16 + (lane >> 2);
        #pragma unroll
        for (int nf = 0; nf < 4; nf++) {
            int col = bn + wn * 32 + nf * 8 + (lane & 3) * 2;
            float b0 = __ldg(bias + col);
            float b1 = __ldg(bias + col + 1);
            if (row0 < M) {
                float2 o;
                o.x = fmaxf(acc[mf][nf][0] + b0, 0.f);
                o.y = fmaxf(acc[mf][nf][1] + b1, 0.f);
                *reinterpret_cast<float2*>(out + (size_t)row0 * OUT_DIM + col) = o;
            }
            if (row0 + 8 < M) {
                float2 o;
                o.x = fmaxf(acc[mf][nf][2] + b0, 0.f);
                o.y = fmaxf(acc[mf][nf][3] + b1, 0.f);
                *reinterpret_cast<float2*>(out + (size_t)(row0 + 8) * OUT_DIM + col) = o;
            }
        }
    }
}

// ---------------------------------------------------------------------------
extern "C" void kernel_launch(void* const* d_in, const int* in_sizes, int n_in,
                              void* d_out, int out_size) {
    const float* h      = (const float*)d_in[0];
    const float* basis  = (const float*)d_in[1];
    const float* w_comp = (const float*)d_in[2];
    const float* bias   = (const float*)d_in[3];
    const int*   src    = (const int*)d_in[4];
    const int*   dst    = (const int*)d_in[5];
    const int*   etype  = (const int*)d_in[6];
    float* out = (float*)d_out;

    int N = in_sizes[0] / IN_DIM;   // 20000
    int E = in_sizes[4];            // 320000

    static cudaStream_t s1 = nullptr, s2 = nullptr;
    static cudaEvent_t e0 = nullptr, e1 = nullptr, e2 = nullptr;
    static bool init_done = false;
    if (!init_done) {
        cudaFuncSetAttribute(gemm_tc_kernel,
                             cudaFuncAttributeMaxDynamicSharedMemorySize,
                             GEMM_SMEM_BYTES);
        cudaStreamCreateWithFlags(&s1, cudaStreamNonBlocking);
        cudaStreamCreateWithFlags(&s2, cudaStreamNonBlocking);
        cudaEventCreateWithFlags(&e0, cudaEventDisableTiming);
        cudaEventCreateWithFlags(&e1, cudaEventDisableTiming);
        cudaEventCreateWithFlags(&e2, cudaEventDisableTiming);
        init_done = true;
    }

    void* uptr = nullptr;
    cudaGetSymbolAddress(&uptr, g_U);
    __half* btp = nullptr;
    cudaGetSymbolAddress((void**)&btp, g_Bt);

    // fork: memset U on s1; transpose on s2 (joined only before GEMM)
    cudaEventRecord(e0, 0);
    cudaStreamWaitEvent(s1, e0, 0);
    cudaStreamWaitEvent(s2, e0, 0);

    cudaMemsetAsync(uptr, 0, (size_t)M_PAD * K_DIM * sizeof(__half), s1);  // #1
    cudaEventRecord(e1, s1);

    fold_kernel<<<(N * 16 + 255) / 256, 256>>>(h, w_comp, N);              // #2

    transpose_kernel<<<dim3(32, 8), dim3(32, 8), 0, s2>>>(basis);          // #3
    cudaEventRecord(e2, s2);

    cudaStreamWaitEvent(0, e1, 0);   // scatter needs zeroed U (+ fold on main)

    scatter_kernel<<<(E + 15) / 16, 256>>>(src, dst, etype, E);            // #4

    cudaStreamWaitEvent(0, e2, 0);   // GEMM needs Bt

    dim3 grid(OUT_DIM / GBN, M_PAD / GBM);   // (4, 314)
    gemm_tc_kernel<<<grid, 128, GEMM_SMEM_BYTES>>>(btp, bias, out, N);     // #5 (ncu)
}

// round 16
// speedup vs baseline: 1.3463x; 1.0614x over previous
#include <cuda_runtime.h>
#include <cuda_fp16.h>
#include <cstdint>

#define N_NODES   20000
#define M_PAD     20096      // 314 * 64
#define IN_DIM    256
#define OUT_DIM   256
#define FOLD_DIM  128        // 32 q-groups * 4 bases
#define K_DIM     1024       // 8 relations * 128

// Scratch (static device globals — no allocation allowed)
__device__ __half g_hf[N_NODES * FOLD_DIM];        // folded h  [N, 128] fp16
__device__ __half g_U [(size_t)M_PAD * K_DIM];     // aggregated [M_PAD, 1024] fp16
__device__ __half g_Bt[(size_t)OUT_DIM * K_DIM];   // basis^T, K-major, fp16

// ---------------------------------------------------------------------------
// Kernel 1: fold h with w_comp.  hf[n, q*4+b] = sum_p h[n, q*8+p] * w_comp[p,b]
// Each thread handles TWO q-groups (4 independent float4 loads -> MLP 4).
// ---------------------------------------------------------------------------
__global__ void fold_kernel(const float* __restrict__ h,
                            const float* __restrict__ w_comp, int N) {
    __shared__ float wc[32];
    if (threadIdx.x < 32) wc[threadIdx.x] = w_comp[threadIdx.x];
    __syncthreads();

    int idx = blockIdx.x * blockDim.x + threadIdx.x;   // over N*16 (n, q-pair)
    if (idx >= N * 16) return;
    int n  = idx >> 4;
    int q2 = idx & 15;

    const float4* hp = reinterpret_cast<const float4*>(
        h + (size_t)n * IN_DIM + q2 * 16);
    float4 hv4[4];
    hv4[0] = hp[0]; hv4[1] = hp[1]; hv4[2] = hp[2]; hv4[3] = hp[3];
    const float* hv = reinterpret_cast<const float*>(hv4);

    __half2 o[4];
    #pragma unroll
    for (int g = 0; g < 2; g++) {
        float r[4];
        #pragma unroll
        for (int b = 0; b < 4; b++) {
            float s = 0.f;
            #pragma unroll
            for (int p = 0; p < 8; p++) s += hv[g * 8 + p] * wc[p * 4 + b];
            r[b] = s;
        }
        o[g * 2 + 0] = __floats2half2_rn(r[0], r[1]);
        o[g * 2 + 1] = __floats2half2_rn(r[2], r[3]);
    }
    *reinterpret_cast<uint4*>(g_hf + (size_t)n * FOLD_DIM + q2 * 8) =
        *reinterpret_cast<const uint4*>(o);
}

// ---------------------------------------------------------------------------
// Kernel 2: transpose basis [1024,256] -> g_Bt [256,1024] (K-major) as fp16.
// ---------------------------------------------------------------------------
__global__ void transpose_kernel(const float* __restrict__ basis) {
    __shared__ float t[32][33];
    int bx = blockIdx.x;
    int by = blockIdx.y;
    int x = threadIdx.x;
    int y = threadIdx.y;
    #pragma unroll
    for (int i = 0; i < 4; i++)
        t[y + i * 8][x] = basis[(size_t)(bx * 32 + y + i * 8) * OUT_DIM + by * 32 + x];
    __syncthreads();
    #pragma unroll
    for (int i = 0; i < 4; i++)
        g_Bt[(size_t)(by * 32 + y + i * 8) * K_DIM + bx * 32 + x] =
            __float2half_rn(t[x][y + i * 8]);
}

// ---------------------------------------------------------------------------
// Kernel 3: edge scatter, fp16. R13 per-edge layout (16 contiguous lanes,
// uint4 + one v4 RED) but TWO edges per thread for 2x MLP.
// ---------------------------------------------------------------------------
__global__ void scatter_kernel(const int* __restrict__ src,
                               const int* __restrict__ dst,
                               const int* __restrict__ etype, int E) {
    int warp = (blockIdx.x * blockDim.x + threadIdx.x) >> 5;
    int lane = threadIdx.x & 31;
    int e0 = warp * 4 + (lane >> 4);     // edges e0 and e0+2 for this thread
    int e1 = e0 + 2;
    int l = lane & 15;
    if (e0 >= E) return;

    int s0 = __ldg(src + e0);
    int d0 = __ldg(dst + e0);
    int r0 = __ldg(etype + e0);

    bool has1 = (e1 < E);
    int s1 = 0, d1 = 0, r1 = 0;
    if (has1) {
        s1 = __ldg(src + e1);
        d1 = __ldg(dst + e1);
        r1 = __ldg(etype + e1);
    }

    uint4 v0 = *reinterpret_cast<const uint4*>(g_hf + (size_t)s0 * FOLD_DIM + l * 8);
    uint4 v1 = has1
        ? *reinterpret_cast<const uint4*>(g_hf + (size_t)s1 * FOLD_DIM + l * 8)
        : make_uint4(0, 0, 0, 0);

    __half* up0 = g_U + (size_t)d0 * K_DIM + r0 * FOLD_DIM + l * 8;
    asm volatile("red.global.add.noftz.v4.f16x2 [%0], {%1, %2, %3, %4};"
                 :: "l"(up0), "r"(v0.x), "r"(v0.y), "r"(v0.z), "r"(v0.w)
                 : "memory");
    if (has1) {
        __half* up1 = g_U + (size_t)d1 * K_DIM + r1 * FOLD_DIM + l * 8;
        asm volatile("red.global.add.noftz.v4.f16x2 [%0], {%1, %2, %3, %4};"
                     :: "l"(up1), "r"(v1.x), "r"(v1.y), "r"(v1.z), "r"(v1.w)
                     : "memory");
    }
}

// ---------------------------------------------------------------------------
// Kernel 4: fp16 tensor-core GEMM + bias + relu.
// out[M,256] = relu(U[M,1024] @ Bt^T + bias)
// CTA 64x64, 128 threads, 2x2 warp grid (warp tile 32x32), 4 CTAs/SM (smem).
// BK=64, THREE-stage cp.async pipeline with wait_group(1) (consumed stage was
// issued two compute-phases earlier -> DRAM latency covered). Fully unrolled
// k-loop keeps every stage/gmem offset a compile-time literal.
// ---------------------------------------------------------------------------
#define GBM 64
#define GBN 64
#define GBK 64
#define STAGE_BYTES (GBM * 128)                       // 8192 B per operand-stage
#define STAGES 3
#define GEMM_SMEM_BYTES (2 * STAGES * STAGE_BYTES)    // 49152 B

#define SWZ(o) ((o) ^ (((o) >> 3) & 0x70))

__device__ __forceinline__ uint32_t smem_u32(const void* p) {
    return (uint32_t)__cvta_generic_to_shared(p);
}

__global__ __launch_bounds__(128, 4)
void gemm_tc_kernel(const __half* __restrict__ Bt,
                    const float* __restrict__ bias,
                    float* __restrict__ out, int M) {
    extern __shared__ char smem[];
    char* As = smem;                           // stages at +0, +8192, +16384
    char* Bs = smem + STAGES * STAGE_BYTES;    // stages at +0, +8192, +16384

    int tid  = threadIdx.x;
    int lane = tid & 31;
    int warp = tid >> 5;
    int wm = warp & 1;                      // rows wm*32
    int wn = warp >> 1;                     // cols wn*32
    int bm = blockIdx.y * GBM;
    int bn = blockIdx.x * GBN;

    float acc[2][4][4];                     // [mf][nf][4]
    #pragma unroll
    for (int mf = 0; mf < 2; mf++)
        #pragma unroll
        for (int nf = 0; nf < 4; nf++)
            #pragma unroll
            for (int i = 0; i < 4; i++) acc[mf][nf][i] = 0.f;

    // ---- staging bases (all further offsets are compile-time literals) ----
    int r0  = tid >> 3;                    // 0..15; covers rows r0 + 16i
    int seg = tid & 7;
    uint32_t c_st = (uint32_t)(r0 & 7) << 4;
    uint32_t daA = smem_u32(As) + r0 * 128 + ((uint32_t)(seg * 16) ^ c_st);
    uint32_t daB = smem_u32(Bs) + r0 * 128 + ((uint32_t)(seg * 16) ^ c_st);
    const __half* gA = g_U + (size_t)(bm + r0) * K_DIM + seg * 8;
    const __half* gB = Bt + (size_t)(bn + r0) * K_DIM + seg * 8;

    // STGOFF, KOFF literals (full unroll below guarantees this)
    #define ISSUE_STAGE(STGOFF, KOFF)                                           \
        do {                                                                    \
            _Pragma("unroll")                                                   \
            for (int i = 0; i < 4; i++) {                                       \
                asm volatile("cp.async.cg.shared.global [%0], [%1], 16;"        \
                             :: "r"(daA + (STGOFF) + i * 2048),                 \
                                "l"(gA + (KOFF) + i * 16 * K_DIM) : "memory");  \
                asm volatile("cp.async.cg.shared.global [%0], [%1], 16;"        \
                             :: "r"(daB + (STGOFF) + i * 2048),                 \
                                "l"(gB + (KOFF) + i * 16 * K_DIM) : "memory");  \
            }                                                                   \
            asm volatile("cp.async.commit_group;" ::: "memory");                \
        } while (0)

    // ---- fragment LDSM addresses, stage 0 (loop-invariant) ----
    int frow = lane & 15;
    int fkb  = (lane >> 4) * 16;
    uint32_t aaddr[2][4], baddr[2][4];
    {
        uint32_t abase = smem_u32(As);
        uint32_t bbase = smem_u32(Bs);
        #pragma unroll
        for (int mf = 0; mf < 2; mf++) {
            int row = wm * 32 + mf * 16 + frow;
            uint32_t c = (uint32_t)(row & 7) << 4;
            #pragma unroll
            for (int ks = 0; ks < 4; ks++)
                aaddr[mf][ks] = abase + row * 128 + ((uint32_t)(ks * 32 + fkb) ^ c);
        }
        #pragma unroll
        for (int p = 0; p < 2; p++) {
            int row = wn * 32 + p * 16 + frow;
            uint32_t c = (uint32_t)(row & 7) << 4;
            #pragma unroll
            for (int ks = 0; ks < 4; ks++)
                baddr[p][ks] = bbase + row * 128 + ((uint32_t)(ks * 32 + fkb) ^ c);
        }
    }

    #define COMPUTE(COFF)                                                           \
        do {                                                                        \
            _Pragma("unroll")                                                       \
            for (int ks = 0; ks < 4; ks++) {                                        \
                uint32_t afr[2][4];                                                 \
                _Pragma("unroll")                                                   \
                for (int mf = 0; mf < 2; mf++)                                      \
                    asm volatile(                                                   \
                        "ldmatrix.sync.aligned.m8n8.x4.shared.b16 {%0,%1,%2,%3}, [%4];" \
                        : "=r"(afr[mf][0]), "=r"(afr[mf][1]),                       \
                          "=r"(afr[mf][2]), "=r"(afr[mf][3])                        \
                        : "r"(aaddr[mf][ks] + (COFF)));                             \
                uint32_t bfr[4][2];                                                 \
                _Pragma("unroll")                                                   \
                for (int p = 0; p < 2; p++) {                                       \
                    uint32_t r0_, r1_, r2_, r3_;                                    \
                    asm volatile(                                                   \
                        "ldmatrix.sync.aligned.m8n8.x4.shared.b16 {%0,%1,%2,%3}, [%4];" \
                        : "=r"(r0_), "=r"(r1_), "=r"(r2_), "=r"(r3_)                \
                        : "r"(baddr[p][ks] + (COFF)));                              \
                    bfr[2 * p][0] = r0_; bfr[2 * p + 1][0] = r1_;                   \
                    bfr[2 * p][1] = r2_; bfr[2 * p + 1][1] = r3_;                   \
                }                                                                   \
                _Pragma("unroll")                                                   \
                for (int mf = 0; mf < 2; mf++)                                      \
                    _Pragma("unroll")                                               \
                    for (int nf = 0; nf < 4; nf++)                                  \
                        asm volatile(                                               \
                            "mma.sync.aligned.m16n8k16.row.col.f32.f16.f16.f32 "    \
                            "{%0,%1,%2,%3}, {%4,%5,%6,%7}, {%8,%9}, {%0,%1,%2,%3};" \
                            : "+f"(acc[mf][nf][0]), "+f"(acc[mf][nf][1]),           \
                              "+f"(acc[mf][nf][2]), "+f"(acc[mf][nf][3])            \
                            : "r"(afr[mf][0]), "r"(afr[mf][1]),                     \
                              "r"(afr[mf][2]), "r"(afr[mf][3]),                     \
                              "r"(bfr[nf][0]), "r"(bfr[nf][1]));                    \
            }                                                                       \
        } while (0)

    // prologue: stages 0,1 <- chunks 0,1 (commit-group g fills chunk g)
    ISSUE_STAGE(0, 0);
    ISSUE_STAGE(STAGE_BYTES, 64);

    // fully unrolled: 16 chunks; stage = it%3, all offsets literal.
    // wait_group(1) completes chunk `it` (group it) while chunk it+1 stays
    // in flight; last iteration needs wait_group(0).
    #pragma unroll
    for (int it = 0; it < 16; ++it) {
        if (it < 15)
            asm volatile("cp.async.wait_group 1;" ::: "memory");
        else
            asm volatile("cp.async.wait_group 0;" ::: "memory");
        __syncthreads();

        if (it + 2 < 16)
            ISSUE_STAGE(((it + 2) % 3) * STAGE_BYTES, (it + 2) * 64);

        COMPUTE((it % 3) * STAGE_BYTES);
    }

    // epilogue: + bias, relu
    #pragma unroll
    for (int mf = 0; mf < 2; mf++) {
        int row0 = bm + wm * 32 + mf * 16 + (lane >> 2);
        #pragma unroll
        for (int nf = 0; nf < 4; nf++) {
            int col = bn + wn * 32 + nf * 8 + (lane & 3) * 2;
            float b0 = __ldg(bias + col);
            float b1 = __ldg(bias + col + 1);
            if (row0 < M) {
                float2 o;
                o.x = fmaxf(acc[mf][nf][0] + b0, 0.f);
                o.y = fmaxf(acc[mf][nf][1] + b1, 0.f);
                *reinterpret_cast<float2*>(out + (size_t)row0 * OUT_DIM + col) = o;
            }
            if (row0 + 8 < M) {
                float2 o;
                o.x = fmaxf(acc[mf][nf][2] + b0, 0.f);
                o.y = fmaxf(acc[mf][nf][3] + b1, 0.f);
                *reinterpret_cast<float2*>(out + (size_t)(row0 + 8) * OUT_DIM + col) = o;
            }
        }
    }
}

// ---------------------------------------------------------------------------
extern "C" void kernel_launch(void* const* d_in, const int* in_sizes, int n_in,
                              void* d_out, int out_size) {
    const float* h      = (const float*)d_in[0];
    const float* basis  = (const float*)d_in[1];
    const float* w_comp = (const float*)d_in[2];
    const float* bias   = (const float*)d_in[3];
    const int*   src    = (const int*)d_in[4];
    const int*   dst    = (const int*)d_in[5];
    const int*   etype  = (const int*)d_in[6];
    float* out = (float*)d_out;

    int N = in_sizes[0] / IN_DIM;   // 20000
    int E = in_sizes[4];            // 320000

    static cudaStream_t s1 = nullptr, s2 = nullptr;
    static cudaEvent_t e0 = nullptr, e1 = nullptr, e2 = nullptr;
    static bool init_done = false;
    if (!init_done) {
        cudaFuncSetAttribute(gemm_tc_kernel,
                             cudaFuncAttributeMaxDynamicSharedMemorySize,
                             GEMM_SMEM_BYTES);
        cudaStreamCreateWithFlags(&s1, cudaStreamNonBlocking);
        cudaStreamCreateWithFlags(&s2, cudaStreamNonBlocking);
        cudaEventCreateWithFlags(&e0, cudaEventDisableTiming);
        cudaEventCreateWithFlags(&e1, cudaEventDisableTiming);
        cudaEventCreateWithFlags(&e2, cudaEventDisableTiming);
        init_done = true;
    }

    void* uptr = nullptr;
    cudaGetSymbolAddress(&uptr, g_U);
    __half* btp = nullptr;
    cudaGetSymbolAddress((void**)&btp, g_Bt);

    // fork: memset U on s1; transpose on s2 (joined only before GEMM)
    cudaEventRecord(e0, 0);
    cudaStreamWaitEvent(s1, e0, 0);
    cudaStreamWaitEvent(s2, e0, 0);

    cudaMemsetAsync(uptr, 0, (size_t)M_PAD * K_DIM * sizeof(__half), s1);  // #1
    cudaEventRecord(e1, s1);

    fold_kernel<<<(N * 16 + 255) / 256, 256>>>(h, w_comp, N);              // #2

    transpose_kernel<<<dim3(32, 8), dim3(32, 8), 0, s2>>>(basis);          // #3
    cudaEventRecord(e2, s2);

    cudaStreamWaitEvent(0, e1, 0);   // scatter needs zeroed U (+ fold on main)

    scatter_kernel<<<(E + 31) / 32, 256>>>(src, dst, etype, E);            // #4

    cudaStreamWaitEvent(0, e2, 0);   // GEMM needs Bt

    dim3 grid(OUT_DIM / GBN, M_PAD / GBM);   // (4, 314)
    gemm_tc_kernel<<<grid, 128, GEMM_SMEM_BYTES>>>(btp, bias, out, N);     // #5 (ncu)
}